// round 14
// baseline (speedup 1.0000x reference)
#include <cuda_runtime.h>
#include <cstdint>

#define R  5
#define E  50000
#define NN 20000      // NU == NI
#define NF 4
#define DN 16
#define DR 64
#define DO 64
#define TILE_E 128
// TAU = 0.5 -> 1/TAU = 2.0f

// ---------------- scratch (device globals; no allocation) ----------------
__device__ __align__(16) float g_blended[R * E];
__device__ __align__(16) float g_norm_u[NN];
__device__ __align__(16) float g_norm_i[NN];
__device__ __align__(16) float g_hu[R * NN * DN];
__device__ __align__(16) float g_hi[R * NN * DN];
__device__ __align__(16) float g_user_msg[NN * DN];
__device__ __align__(16) float g_item_msg[NN * DN];

__device__ __forceinline__ float dot4(float4 a, float4 b) {
    return a.x * b.x + a.y * b.y + a.z * b.z + a.w * b.w;
}

// vector global reduction (sm_90+): 4 floats in one RED
__device__ __forceinline__ void red_add_v4(float* p, float4 m) {
    asm volatile("red.global.add.v4.f32 [%0], {%1, %2, %3, %4};"
                 :: "l"(p), "f"(m.x), "f"(m.y), "f"(m.z), "f"(m.w)
                 : "memory");
}

// LDS.128 delivering two packed f32x2 (no pack MOVs)
#define LDS_V2_U64(lo, hi, addr) \
    asm("ld.shared.v2.b64 {%0, %1}, [%2];" : "=l"(lo), "=l"(hi) : "r"(addr))

// packed dual FMA: acc.{lo,hi} += a.{lo,hi} * b.{lo,hi}
__device__ __forceinline__ void ffma2(uint64_t& acc, uint64_t a, uint64_t b) {
    asm("fma.rn.f32x2 %0, %1, %2, %0;" : "+l"(acc) : "l"(a), "l"(b));
}

__device__ __forceinline__ float hsum2(uint64_t acc) {
    float lo, hi;
    asm("mov.b64 {%0, %1}, %2;" : "=f"(lo), "=f"(hi) : "l"(acc));
    return lo + hi;
}

// ---------------- kernel 1/2: proj one side (+ fused zeroing on side 0) ----------------
__global__ void proj_kernel(const float* __restrict__ h_in,
                            const float* __restrict__ w_in,
                            float* __restrict__ h_out,
                            const int* __restrict__ kptr,
                            int do_zero) {
    int idx = blockIdx.x * blockDim.x + threadIdx.x;

    if (do_zero) {
        float4 z = make_float4(0.f, 0.f, 0.f, 0.f);
        if (idx < NN * DN / 4) {
            reinterpret_cast<float4*>(g_user_msg)[idx] = z;
            reinterpret_cast<float4*>(g_item_msg)[idx] = z;
        }
        if (idx < NN / 4) {
            reinterpret_cast<float4*>(g_norm_u)[idx] = z;
            reinterpret_cast<float4*>(g_norm_i)[idx] = z;
        }
    }

    if (idx >= R * NN) return;
    int r = idx / NN, n = idx % NN;
    int kk = *kptr;

    const float* h = h_in + ((size_t)(kk * R + r) * NN + n) * DN;
    const float* W = w_in + r * DN * DN;
    float* out = h_out + ((size_t)r * NN + n) * DN;

    float x[DN];
#pragma unroll
    for (int i = 0; i < 4; i++) {
        float4 t = reinterpret_cast<const float4*>(h)[i];
        x[4*i+0] = t.x; x[4*i+1] = t.y; x[4*i+2] = t.z; x[4*i+3] = t.w;
    }
#pragma unroll
    for (int o = 0; o < DN; o++) {
        float acc = 0.f;
#pragma unroll
        for (int d = 0; d < DN; d++) acc += x[d] * __ldg(&W[o * DN + d]);
        out[o] = acc;
    }
}

// ---------------- kernel 3: blend-lite (4 edges/warp, 8 lanes/edge) ----------------
__global__ __launch_bounds__(256)
void blend_kernel(const float* __restrict__ user_h,
                  const float* __restrict__ item_h,
                  const float* __restrict__ user_hsum,
                  const float* __restrict__ item_hsum,
                  const float* __restrict__ review_feat,
                  const float* __restrict__ prototypes,
                  const float* __restrict__ eta,
                  const int* __restrict__ edge_src,
                  const int* __restrict__ edge_dst,
                  const int* __restrict__ kptr) {
    __shared__ float4 sproto[NF * DR / 4];   // 64 float4
    int tid = threadIdx.x;
    int r = blockIdx.y;
    if (tid < 64) sproto[tid] = reinterpret_cast<const float4*>(prototypes)[tid];
    __syncthreads();

    int warp = tid >> 5, lane = tid & 31, g = lane >> 3, sub = lane & 7;
    int e = (blockIdx.x * 8 + warp) * 4 + g;
    bool valid = e < E;
    int ec = valid ? e : E - 1;
    int kk = *kptr;
    int id = r * E + ec;
    int src = edge_src[id];
    int dst = edge_dst[id];

    // ---- sim_all denominator (hsum, 64 floats each side) ----
    const float4* ra = reinterpret_cast<const float4*>(user_hsum + ((size_t)r * NN + src) * (NF * DN));
    const float4* ca = reinterpret_cast<const float4*>(item_hsum + ((size_t)r * NN + dst) * (NF * DN));
    float p = dot4(ra[2 * sub], ca[2 * sub]) + dot4(ra[2 * sub + 1], ca[2 * sub + 1]);
    p += __shfl_xor_sync(0xffffffffu, p, 1);        // full dot for factor f = sub/2
    float ex = __expf(2.f * p);
    ex += __shfl_xor_sync(0xffffffffu, ex, 2);
    ex += __shfl_xor_sync(0xffffffffu, ex, 4);
    float denom_sim = ex;                           // each f counted once

    // ---- cosine sim (lanes sub<4 of each group) ----
    float uu = 0.f, vv = 0.f, uv = 0.f;
    if (sub < 4) {
        float4 a = reinterpret_cast<const float4*>(user_h + ((size_t)(kk * R + r) * NN + src) * DN)[sub];
        float4 b = reinterpret_cast<const float4*>(item_h + ((size_t)(kk * R + r) * NN + dst) * DN)[sub];
        uu = dot4(a, a); vv = dot4(b, b); uv = dot4(a, b);
    }
    uu += __shfl_xor_sync(0xffffffffu, uu, 1); uu += __shfl_xor_sync(0xffffffffu, uu, 2);
    vv += __shfl_xor_sync(0xffffffffu, vv, 1); vv += __shfl_xor_sync(0xffffffffu, vv, 2);
    uv += __shfl_xor_sync(0xffffffffu, uv, 1); uv += __shfl_xor_sync(0xffffffffu, uv, 2);

    // ---- anchors: stream rf row (256 floats), 8-lane-coalesced ----
    const float4* rf4 = reinterpret_cast<const float4*>(review_feat + (size_t)id * (NF * DR));
    float af[4] = {0.f, 0.f, 0.f, 0.f};
#pragma unroll
    for (int j = 0; j < 8; j++) {
        float4 q = rf4[sub + 8 * j];
        af[j >> 1] += dot4(q, sproto[sub + 8 * j]);
    }
#pragma unroll
    for (int o = 1; o < 8; o <<= 1) {
        af[0] += __shfl_xor_sync(0xffffffffu, af[0], o);
        af[1] += __shfl_xor_sync(0xffffffffu, af[1], o);
        af[2] += __shfl_xor_sync(0xffffffffu, af[2], o);
        af[3] += __shfl_xor_sync(0xffffffffu, af[3], o);
    }

    // ---- blended weight (lane sub==0 of each group) ----
    if (sub == 0 && valid) {
        float nu = fmaxf(sqrtf(uu), 1e-12f);
        float nv = fmaxf(sqrtf(vv), 1e-12f);
        float sim_k = 2.f * uv / (nu * nv);
        float exp_sim = __expf(sim_k) / denom_sim;

        float a0 = 2.f * af[0], a1 = 2.f * af[1], a2 = 2.f * af[2], a3 = 2.f * af[3];
        float denom_a = __expf(a0) + __expf(a1) + __expf(a2) + __expf(a3);
        float ak = (kk == 0) ? a0 : (kk == 1) ? a1 : (kk == 2) ? a2 : a3;
        float exp_anchor = __expf(ak) / denom_a;

        float gs = 1.f / (1.f + __expf(-eta[id]));
        float bl = gs * exp_anchor + (1.f - gs) * exp_sim;

        g_blended[id] = bl;
        atomicAdd(&g_norm_u[src], bl);
        atomicAdd(&g_norm_i[dst], bl);
    }
}

// ---------------- kernel 4: tiled GEMM (packed f32x2) + fused scatter ----------------
// Epilogue gathers (h) prefetched into registers BEFORE the FMA loop.
__global__ __launch_bounds__(256)
void gemm_scatter_kernel(const float* __restrict__ review_feat,
                         const float* __restrict__ rw_fwd,
                         const float* __restrict__ rw_rev,
                         const int* __restrict__ edge_src,
                         const int* __restrict__ edge_dst,
                         const int* __restrict__ kptr,
                         float* __restrict__ out_int_dist) {
    __shared__ float4 sW[32 * 16];     // rows 0-15 Wf, 16-31 Wr
    __shared__ float4 sX[16 * 129];    // transposed X: [d4][edge], pitch 129
    __shared__ float  sw_s[TILE_E];
    __shared__ int    ssrc[TILE_E];
    __shared__ int    sdst[TILE_E];

    int r = blockIdx.y;
    int tid = threadIdx.x;
    int e0 = blockIdx.x * TILE_E;
    int kk = *kptr;

    // stage W (stacked)
    {
        const float4* wf4 = reinterpret_cast<const float4*>(rw_fwd + r * DN * DR);
        const float4* wr4 = reinterpret_cast<const float4*>(rw_rev + r * DN * DR);
        for (int i = tid; i < 512; i += 256)
            sW[i] = (i < 256) ? wf4[i] : wr4[i - 256];
    }
    // stage X transposed (coalesced gmem)
    {
        int d4 = tid & 15, erow = tid >> 4;
#pragma unroll
        for (int pss = 0; pss < 8; pss++) {
            int e = erow + 16 * pss;
            int ge = e0 + e;
            float4 v = make_float4(0.f, 0.f, 0.f, 0.f);
            if (ge < E)
                v = reinterpret_cast<const float4*>(review_feat)[
                        ((size_t)(r * E + ge) * NF + kk) * (DR / 4) + d4];
            sX[d4 * 129 + e] = v;
        }
    }
    // per-edge normalized weight + int_dist (threads 0-127)
    if (tid < TILE_E) {
        int ge = e0 + tid;
        float w = 0.f; int s = 0, d = 0;
        if (ge < E) {
            int id = r * E + ge;
            s = edge_src[id]; d = edge_dst[id];
            w = g_blended[id] * rsqrtf(g_norm_u[s] * g_norm_i[d]);
            out_int_dist[id] = w;
        }
        sw_s[tid] = w; ssrc[tid] = s; sdst[tid] = d;
    }
    __syncthreads();

    uint32_t sW_b = (uint32_t)__cvta_generic_to_shared(sW);
    uint32_t sX_b = (uint32_t)__cvta_generic_to_shared(sX);

    int eq = tid & 31;
    int oo = (tid >> 5) & 3;   // output octet (uniform per warp)
    int eh = tid >> 7;         // edge half
    bool fwd = oo < 2;         // outputs 0-15 = m_fwd, 16-31 = m_rev
    int half = oo & 1;         // which 8-float half of the 16-dim message

    // ---- prefetch epilogue gathers (hide ~600cyc latency under the FMA loop) ----
    float wv_p[2]; float4 h0_p[2], h1_p[2]; float* tgt_p[2]; bool val_p[2];
#pragma unroll
    for (int j = 0; j < 2; j++) {
        int et = eq + 32 * (2 * eh + j);
        val_p[j] = (e0 + et) < E;
        wv_p[j] = sw_s[et];
        int s = ssrc[et], d = sdst[et];
        const float4* h4 = reinterpret_cast<const float4*>(
            fwd ? g_hu + ((size_t)r * NN + s) * DN
                : g_hi + ((size_t)r * NN + d) * DN) + 2 * half;
        h0_p[j] = __ldg(h4); h1_p[j] = __ldg(h4 + 1);
        tgt_p[j] = (fwd ? g_item_msg + (size_t)d * DN
                        : g_user_msg + (size_t)s * DN) + 8 * half;
    }

    uint64_t acc[2][8] = {};   // packed {even,odd} partial sums
#pragma unroll
    for (int d4 = 0; d4 < 16; d4++) {
        uint64_t xl[2], xh[2];
        LDS_V2_U64(xl[0], xh[0], sX_b + (uint32_t)(d4 * 129 + eq + 32 * (2 * eh + 0)) * 16u);
        LDS_V2_U64(xl[1], xh[1], sX_b + (uint32_t)(d4 * 129 + eq + 32 * (2 * eh + 1)) * 16u);
#pragma unroll
        for (int og = 0; og < 2; og++) {
            uint64_t wl[4], wh[4];
#pragma unroll
            for (int o = 0; o < 4; o++)
                LDS_V2_U64(wl[o], wh[o],
                           sW_b + (uint32_t)(((8 * oo + 4 * og + o) * 16 + d4)) * 16u);
#pragma unroll
            for (int j = 0; j < 2; j++)
#pragma unroll
                for (int o = 0; o < 4; o++) {
                    ffma2(acc[j][4 * og + o], xl[j], wl[o]);
                    ffma2(acc[j][4 * og + o], xh[j], wh[o]);
                }
        }
    }

#pragma unroll
    for (int j = 0; j < 2; j++) {
        if (!val_p[j]) continue;
        float a[8];
#pragma unroll
        for (int o = 0; o < 8; o++) a[o] = hsum2(acc[j][o]);
        float wv = wv_p[j];
        float4 h0 = h0_p[j], h1 = h1_p[j];
        red_add_v4(tgt_p[j], make_float4((a[0] + h0.x) * wv, (a[1] + h0.y) * wv,
                                         (a[2] + h0.z) * wv, (a[3] + h0.w) * wv));
        red_add_v4(tgt_p[j] + 4, make_float4((a[4] + h1.x) * wv, (a[5] + h1.y) * wv,
                                             (a[6] + h1.z) * wv, (a[7] + h1.w) * wv));
    }
}

// ---------------- kernel 5: leaky_relu + FC, tiled (128 nodes/block, 512 thr) ----------------
__global__ __launch_bounds__(512)
void fc_kernel(const float* __restrict__ ufc_w, const float* __restrict__ ufc_b,
               const float* __restrict__ ifc_w, const float* __restrict__ ifc_b,
               float* __restrict__ out) {
    __shared__ float4 sW[DO * 4];    // weight row o at sW[o*4 + i]
    __shared__ float  sB[DO];
    __shared__ float4 sM[128 * 5];   // node msg, pitch 5 float4 (bank spread)

    int side = blockIdx.y;
    int tid = threadIdx.x;
    int n0 = blockIdx.x * 128;

    {
        const float4* W4 = reinterpret_cast<const float4*>(side ? ifc_w : ufc_w);
        const float*  B  = side ? ifc_b : ufc_b;
        if (tid < DO * 4) sW[tid] = W4[tid];
        if (tid < DO) sB[tid] = B[tid];
    }
    // stage msgs: 128 nodes x 4 float4, coalesced; leaky once per element
    {
        int node = tid >> 2, i = tid & 3;
        int n = n0 + node;
        const float4* msrc = reinterpret_cast<const float4*>(side ? g_item_msg : g_user_msg);
        float4 m = make_float4(0.f, 0.f, 0.f, 0.f);
        if (n < NN) m = msrc[n * 4 + i];
        m.x = m.x >= 0.f ? m.x : 0.1f * m.x;
        m.y = m.y >= 0.f ? m.y : 0.1f * m.y;
        m.z = m.z >= 0.f ? m.z : 0.1f * m.z;
        m.w = m.w >= 0.f ? m.w : 0.1f * m.w;
        sM[node * 5 + i] = m;
    }
    __syncthreads();

    int node = tid & 127, oq = tid >> 7;   // oq uniform per 4-warp group
    int n = n0 + node;
    if (n >= NN) return;

    float4 m0 = sM[node * 5 + 0], m1 = sM[node * 5 + 1];
    float4 m2 = sM[node * 5 + 2], m3 = sM[node * 5 + 3];

    float4* outp = reinterpret_cast<float4*>(
        out + ((size_t)(side * NN + n)) * DO + oq * 16);
#pragma unroll
    for (int ob = 0; ob < 4; ob++) {
        float4 ov;
        int o0 = oq * 16 + 4 * ob;
        ov.x = sB[o0+0] + dot4(m0, sW[(o0+0)*4+0]) + dot4(m1, sW[(o0+0)*4+1])
                        + dot4(m2, sW[(o0+0)*4+2]) + dot4(m3, sW[(o0+0)*4+3]);
        ov.y = sB[o0+1] + dot4(m0, sW[(o0+1)*4+0]) + dot4(m1, sW[(o0+1)*4+1])
                        + dot4(m2, sW[(o0+1)*4+2]) + dot4(m3, sW[(o0+1)*4+3]);
        ov.z = sB[o0+2] + dot4(m0, sW[(o0+2)*4+0]) + dot4(m1, sW[(o0+2)*4+1])
                        + dot4(m2, sW[(o0+2)*4+2]) + dot4(m3, sW[(o0+2)*4+3]);
        ov.w = sB[o0+3] + dot4(m0, sW[(o0+3)*4+0]) + dot4(m1, sW[(o0+3)*4+1])
                        + dot4(m2, sW[(o0+3)*4+2]) + dot4(m3, sW[(o0+3)*4+3]);
        outp[ob] = ov;
    }
}

// ---------------- launch ----------------
extern "C" void kernel_launch(void* const* d_in, const int* in_sizes, int n_in,
                              void* d_out, int out_size) {
    const float* user_h      = (const float*)d_in[0];
    const float* item_h      = (const float*)d_in[1];
    const float* user_hsum   = (const float*)d_in[2];
    const float* item_hsum   = (const float*)d_in[3];
    const float* review_feat = (const float*)d_in[4];
    const float* prototypes  = (const float*)d_in[5];
    const float* eta         = (const float*)d_in[6];
    const float* node_w_fwd  = (const float*)d_in[7];
    const float* review_w_fwd= (const float*)d_in[8];
    const float* node_w_rev  = (const float*)d_in[9];
    const float* review_w_rev= (const float*)d_in[10];
    const float* ufc_w       = (const float*)d_in[11];
    const float* ufc_b       = (const float*)d_in[12];
    const float* ifc_w       = (const float*)d_in[13];
    const float* ifc_b       = (const float*)d_in[14];
    const int*   edge_src    = (const int*)d_in[15];
    const int*   edge_dst    = (const int*)d_in[16];
    const int*   kptr        = (const int*)d_in[17];

    float* out = (float*)d_out;
    float* out_int = out + (size_t)2 * NN * DO;   // int_dist after ufeat+ifeat

    // launches 1, 2: proj (zeroing fused into launch 1)
    int gp = (R * NN + 255) / 256;
    float* g_hu_p; cudaGetSymbolAddress((void**)&g_hu_p, g_hu);
    float* g_hi_p; cudaGetSymbolAddress((void**)&g_hi_p, g_hi);
    proj_kernel<<<gp, 256>>>(user_h, node_w_fwd, g_hu_p, kptr, 1);
    proj_kernel<<<gp, 256>>>(item_h, node_w_rev, g_hi_p, kptr, 0);

    // launch 3: blend-lite
    dim3 gb((E + 31) / 32, R);   // 32 edges per 256-thread block
    blend_kernel<<<gb, 256>>>(user_h, item_h, user_hsum, item_hsum,
                              review_feat, prototypes, eta,
                              edge_src, edge_dst, kptr);

    // launch 4: fused GEMM + scatter (profiled slot)
    dim3 gg((E + TILE_E - 1) / TILE_E, R);
    gemm_scatter_kernel<<<gg, 256>>>(review_feat, review_w_fwd, review_w_rev,
                                     edge_src, edge_dst, kptr, out_int);

    // launch 5: tiled FC
    dim3 gf((NN + 127) / 128, 2);
    fc_kernel<<<gf, 512>>>(ufc_w, ufc_b, ifc_w, ifc_b, out);
}